// round 10
// baseline (speedup 1.0000x reference)
#include <cuda_runtime.h>
#include <cuda_bf16.h>
#include <math.h>
#include <stdint.h>

// Problem constants
static constexpr int Tt   = 2048;   // B*S tokens
static constexpr int Bb   = 2;
static constexpr int Ss   = 1024;
static constexpr int Dd   = 2048;
static constexpr int Hh   = 32;
static constexpr int HKVc = 8;
static constexpr int HDc  = 64;
static constexpr int QKVN = 3072;   // (H + 2*HKV)*HD
static constexpr int Ii   = 1024;
static constexpr int Ec   = 8;

// ---------------- scratch (device globals; no allocation) ----------------
__device__ float g_h   [(size_t)Tt * Dd];
__device__ float g_qkv [(size_t)Tt * QKVN];
__device__ float g_attn[(size_t)Tt * Dd];
__device__ float g_h1  [(size_t)Tt * Dd];
__device__ float g_g   [(size_t)Tt * Dd];
__device__ float g_sg  [(size_t)Tt * Ii];
__device__ float g_su  [(size_t)Tt * Ii];
__device__ float g_sh  [(size_t)Tt * Dd];
__device__ float g_xe  [(size_t)Ec * Tt * Dd];
__device__ float g_gu  [(size_t)Ec * Tt * 2 * Ii];
__device__ float g_hid [(size_t)Ec * Tt * Ii];
__device__ int   g_cnt [Ec];
__device__ int   g_rows[Ec * Tt];
__device__ float g_wt  [Ec * Tt];

// ---------------- helpers ----------------
__device__ __forceinline__ uint32_t f2tf32(float f) {
    uint32_t r;
    asm("cvt.rna.tf32.f32 %0, %1;" : "=r"(r) : "f"(f));
    return r;
}

// Split fp32 into tf32 hi + tf32 lo (exact residual: hi has low mantissa bits zero)
__device__ __forceinline__ void split_tf32(float v, uint32_t& hi, uint32_t& lo) {
    uint32_t h = f2tf32(v);
    lo = f2tf32(v - __uint_as_float(h));
    hi = h;
}

__device__ __forceinline__ void mma_tf32(float& c0, float& c1, float& c2, float& c3,
                                         uint32_t a0, uint32_t a1, uint32_t a2, uint32_t a3,
                                         uint32_t b0, uint32_t b1) {
    asm volatile("mma.sync.aligned.m16n8k8.row.col.f32.tf32.tf32.f32 "
                 "{%0,%1,%2,%3}, {%4,%5,%6,%7}, {%8,%9}, {%0,%1,%2,%3};"
                 : "+f"(c0), "+f"(c1), "+f"(c2), "+f"(c3)
                 : "r"(a0), "r"(a1), "r"(a2), "r"(a3), "r"(b0), "r"(b1));
}

// ---------------- rmsnorm ----------------
__global__ __launch_bounds__(256) void rmsnorm_kernel(const float* __restrict__ x,
                                                      const float* __restrict__ w,
                                                      float* __restrict__ out)
{
    int t = blockIdx.x;
    const float* xr = x + (size_t)t * Dd;
    float vals[8];
    float ss = 0.f;
#pragma unroll
    for (int i = 0; i < 8; i++) {
        vals[i] = xr[threadIdx.x + i * 256];
        ss += vals[i] * vals[i];
    }
#pragma unroll
    for (int o = 16; o > 0; o >>= 1) ss += __shfl_down_sync(0xffffffffu, ss, o);
    __shared__ float sm[8];
    __shared__ float stot;
    int lane = threadIdx.x & 31, wp = threadIdx.x >> 5;
    if (lane == 0) sm[wp] = ss;
    __syncthreads();
    if (threadIdx.x == 0) {
        float tot = 0.f;
#pragma unroll
        for (int i = 0; i < 8; i++) tot += sm[i];
        stot = rsqrtf(tot / (float)Dd + 1e-5f);
    }
    __syncthreads();
    float sc = stot;
    float* orow = out + (size_t)t * Dd;
#pragma unroll
    for (int i = 0; i < 8; i++) {
        int c = threadIdx.x + i * 256;
        orow[c] = vals[i] * sc * w[c];
    }
}

// =====================================================================
// 3xTF32 tensor-core GEMM (tf32x3), fragment-major shared-memory layout.
// C(128x128) per block, KTILE=16, 256 thr = 8 warps (2m x 4n).
// smem stores hi/lo tiles pre-permuted into MMA fragment order:
//   A: [tileM(8)][kk(2)][lane(32)][word(4)]  -> one LDS.128 per tile/thread
//   B: [tileN(16)][kk(2)][lane(32)][word(2)] -> one LDS.64  per tile/thread
// word encodes (row>=8) + 2*(col>=4) for A, (k>=4) for B — identical
// fragment map to the validated round-9 kernel; only addresses moved.
// Static smem: 4 * 8KB = 32KB.
// =====================================================================
#define MMA_GEMM_BODY(Aptr, Bptr, K_, N_)                                      \
    __shared__ uint32_t AsH[2048];                                             \
    __shared__ uint32_t AsL[2048];                                             \
    __shared__ uint32_t BsH[2048];                                             \
    __shared__ uint32_t BsL[2048];                                             \
    const int tid = threadIdx.x;                                               \
    const int lane = tid & 31, warp = tid >> 5;                                \
    const int wm = warp & 1, wn = warp >> 1;                                   \
    const int g = lane >> 2, t = lane & 3;                                     \
    float acc[4][4][4];                                                        \
    _Pragma("unroll") for (int i_ = 0; i_ < 4; i_++)                           \
    _Pragma("unroll") for (int j_ = 0; j_ < 4; j_++)                           \
    _Pragma("unroll") for (int q_ = 0; q_ < 4; q_++) acc[i_][j_][q_] = 0.f;    \
    /* precompute store indices (k0-invariant) */                              \
    int aidx[2][4], bidx[2][4];                                                \
    _Pragma("unroll")                                                          \
    for (int i = 0; i < 2; i++) {                                              \
        int fi = tid + i * 256;                                                \
        int ra = fi >> 2, ca = (fi & 3) * 4;                                   \
        int rb = fi >> 5, cb = (fi & 31) * 4;                                  \
        _Pragma("unroll")                                                      \
        for (int j = 0; j < 4; j++) {                                          \
            int col = ca + j;                                                  \
            int tileM = ra >> 4, r16 = ra & 15;                                \
            int kk2 = col >> 3, c8 = col & 7;                                  \
            int ln = (r16 & 7) * 4 + (c8 & 3);                                 \
            int wd = ((r16 >> 3) & 1) | (((c8 >> 2) & 1) << 1);                \
            aidx[i][j] = (((tileM << 1) | kk2) * 32 + ln) * 4 + wd;            \
            int nc = cb + j;                                                   \
            int tileN = nc >> 3, gg = nc & 7;                                  \
            int kkb = rb >> 3, r8 = rb & 7;                                    \
            int lnb = gg * 4 + (r8 & 3);                                       \
            int wdb = (r8 >> 2) & 1;                                           \
            bidx[i][j] = (((tileN << 1) | kkb) * 32 + lnb) * 2 + wdb;          \
        }                                                                      \
    }                                                                          \
    float4 pav[2], pbv[2];                                                     \
    _Pragma("unroll")                                                          \
    for (int i = 0; i < 2; i++) {                                              \
        int fi = tid + i * 256;                                                \
        int ra = fi >> 2, ca = (fi & 3) * 4;                                   \
        pav[i] = *(const float4*)((Aptr) + (size_t)ra * (K_) + ca);            \
        int rb = fi >> 5, cb = (fi & 31) * 4;                                  \
        pbv[i] = *(const float4*)((Bptr) + (size_t)rb * (N_) + cb);            \
    }                                                                          \
    for (int k0 = 0; k0 < (K_); k0 += 16) {                                    \
        _Pragma("unroll")                                                      \
        for (int i = 0; i < 2; i++) {                                          \
            split_tf32(pav[i].x, AsH[aidx[i][0]], AsL[aidx[i][0]]);            \
            split_tf32(pav[i].y, AsH[aidx[i][1]], AsL[aidx[i][1]]);            \
            split_tf32(pav[i].z, AsH[aidx[i][2]], AsL[aidx[i][2]]);            \
            split_tf32(pav[i].w, AsH[aidx[i][3]], AsL[aidx[i][3]]);            \
            split_tf32(pbv[i].x, BsH[bidx[i][0]], BsL[bidx[i][0]]);            \
            split_tf32(pbv[i].y, BsH[bidx[i][1]], BsL[bidx[i][1]]);            \
            split_tf32(pbv[i].z, BsH[bidx[i][2]], BsL[bidx[i][2]]);            \
            split_tf32(pbv[i].w, BsH[bidx[i][3]], BsL[bidx[i][3]]);            \
        }                                                                      \
        __syncthreads();                                                       \
        if (k0 + 16 < (K_)) {                                                  \
            _Pragma("unroll")                                                  \
            for (int i = 0; i < 2; i++) {                                      \
                int fi = tid + i * 256;                                        \
                int ra = fi >> 2, ca = (fi & 3) * 4;                           \
                pav[i] = *(const float4*)((Aptr) + (size_t)ra * (K_) + k0 + 16 + ca); \
                int rb = fi >> 5, cb = (fi & 31) * 4;                          \
                pbv[i] = *(const float4*)((Bptr) + (size_t)(k0 + 16 + rb) * (N_) + cb); \
            }                                                                  \
        }                                                                      \
        _Pragma("unroll")                                                      \
        for (int kk = 0; kk < 2; kk++) {                                       \
            uint4 ah[4], al[4];                                                \
            _Pragma("unroll")                                                  \
            for (int mt = 0; mt < 4; mt++) {                                   \
                int tileM = wm * 4 + mt;                                       \
                int base = (((tileM << 1) | kk) * 32 + lane) * 4;              \
                ah[mt] = *(const uint4*)&AsH[base];                            \
                al[mt] = *(const uint4*)&AsL[base];                            \
            }                                                                  \
            uint2 bh[4], bl[4];                                                \
            _Pragma("unroll")                                                  \
            for (int nt = 0; nt < 4; nt++) {                                   \
                int tileN = wn * 4 + nt;                                       \
                int base = (((tileN << 1) | kk) * 32 + lane) * 2;              \
                bh[nt] = *(const uint2*)&BsH[base];                            \
                bl[nt] = *(const uint2*)&BsL[base];                            \
            }                                                                  \
            _Pragma("unroll")                                                  \
            for (int mt = 0; mt < 4; mt++)                                     \
                _Pragma("unroll")                                              \
                for (int nt = 0; nt < 4; nt++) {                               \
                    mma_tf32(acc[mt][nt][0], acc[mt][nt][1],                   \
                             acc[mt][nt][2], acc[mt][nt][3],                   \
                             al[mt].x, al[mt].y, al[mt].z, al[mt].w,           \
                             bh[nt].x, bh[nt].y);                              \
                    mma_tf32(acc[mt][nt][0], acc[mt][nt][1],                   \
                             acc[mt][nt][2], acc[mt][nt][3],                   \
                             ah[mt].x, ah[mt].y, ah[mt].z, ah[mt].w,           \
                             bl[nt].x, bl[nt].y);                              \
                    mma_tf32(acc[mt][nt][0], acc[mt][nt][1],                   \
                             acc[mt][nt][2], acc[mt][nt][3],                   \
                             ah[mt].x, ah[mt].y, ah[mt].z, ah[mt].w,           \
                             bh[nt].x, bh[nt].y);                              \
                }                                                              \
        }                                                                      \
        __syncthreads();                                                       \
    }

// MODE 0: C = A@B ; MODE 1: C = Res + A@B
template <int MODE>
__global__ __launch_bounds__(256) void mma_gemm_kernel(const float* __restrict__ A,
                                                       const float* __restrict__ Bm,
                                                       float* __restrict__ C,
                                                       const float* __restrict__ Res,
                                                       int M, int N, int K)
{
    const int n0 = blockIdx.x * 128, m0 = blockIdx.y * 128;
    const float* Ab = A + (size_t)m0 * K;
    const float* Bb_ = Bm + n0;
    MMA_GEMM_BODY(Ab, Bb_, K, N)
#pragma unroll
    for (int mt = 0; mt < 4; mt++) {
#pragma unroll
        for (int nt = 0; nt < 4; nt++) {
            int row0 = m0 + wm * 64 + mt * 16 + g;
            int col  = n0 + wn * 32 + nt * 8 + t * 2;
            float* p0 = C + (size_t)row0 * N + col;
            float* p1 = C + (size_t)(row0 + 8) * N + col;
            if (MODE == 0) {
                *(float2*)p0 = make_float2(acc[mt][nt][0], acc[mt][nt][1]);
                *(float2*)p1 = make_float2(acc[mt][nt][2], acc[mt][nt][3]);
            } else {
                const float* r0 = Res + (size_t)row0 * N + col;
                const float* r1 = Res + (size_t)(row0 + 8) * N + col;
                float2 v0 = *(const float2*)r0, v1 = *(const float2*)r1;
                *(float2*)p0 = make_float2(acc[mt][nt][0] + v0.x, acc[mt][nt][1] + v0.y);
                *(float2*)p1 = make_float2(acc[mt][nt][2] + v1.x, acc[mt][nt][3] + v1.y);
            }
        }
    }
}

// ---------------- RoPE on q (heads 0..31) and k (heads 32..39) --------------
__global__ __launch_bounds__(256) void rope_kernel(float* __restrict__ qkv,
                                                   const float* __restrict__ cache)
{
    int t = blockIdx.x;
    int s = t & (Ss - 1);
    int pi = blockIdx.y * 256 + threadIdx.x;
    if (pi >= (Hh + HKVc) * (HDc / 2)) return;
    int head = pi >> 5;
    int i = pi & 31;
    int col = (head < Hh) ? head * HDc + 2 * i
                          : Hh * HDc + (head - Hh) * HDc + 2 * i;
    float* p = qkv + (size_t)t * QKVN + col;
    float c  = cache[s * HDc + 2 * i];
    float sn = cache[s * HDc + 2 * i + 1];
    float x0 = p[0], x1 = p[1];
    p[0] = x0 * c - x1 * sn;
    p[1] = x1 * c + x0 * sn;
}

// ---------------- flash attention, static smem (<=48KB), KT=32 --------------
__global__ __launch_bounds__(256) void attn_kernel(const float* __restrict__ qkv,
                                                   float* __restrict__ out)
{
    __shared__ float Qs[64 * 68];
    __shared__ float Ks[32 * 68];
    __shared__ float Vs[32 * 68];
    __shared__ float Ps[64 * 36];
    const int qt = blockIdx.x, h = blockIdx.y, b = blockIdx.z;
    const int kvh = h >> 2;
    const int tid = threadIdx.x;
    const int r = tid >> 2, c = tid & 3;
    const int qcol = h * HDc;
    const int kcol = Hh * HDc + kvh * HDc;
    const int vcol = (Hh + HKVc) * HDc + kvh * HDc;

#pragma unroll
    for (int v = 0; v < 4; v++) {
        int fi = tid + v * 256;
        int rr = fi >> 4, c4 = (fi & 15) * 4;
        *(float4*)&Qs[rr * 68 + c4] =
            *(const float4*)(qkv + (size_t)(b * Ss + qt * 64 + rr) * QKVN + qcol + c4);
    }

    float m = -INFINITY, l = 0.f;
    float acc[16];
#pragma unroll
    for (int i = 0; i < 16; i++) acc[i] = 0.f;

    const int ntiles = 2 * (qt + 1);
    const int qglob = qt * 64 + r;
    for (int kt = 0; kt < ntiles; kt++) {
        const int k0 = kt * 32;
        __syncthreads();
#pragma unroll
        for (int v = 0; v < 2; v++) {
            int fi = tid + v * 256;
            int rr = fi >> 4, c4 = (fi & 15) * 4;
            size_t base = (size_t)(b * Ss + k0 + rr) * QKVN;
            *(float4*)&Ks[rr * 68 + c4] = *(const float4*)(qkv + base + kcol + c4);
            *(float4*)&Vs[rr * 68 + c4] = *(const float4*)(qkv + base + vcol + c4);
        }
        __syncthreads();

        float s[8];
#pragma unroll
        for (int j = 0; j < 8; j++) s[j] = 0.f;
#pragma unroll 4
        for (int d = 0; d < 64; d += 4) {
            float4 qv = *(const float4*)&Qs[r * 68 + d];
#pragma unroll
            for (int j = 0; j < 8; j++) {
                float4 kv = *(const float4*)&Ks[(c * 8 + j) * 68 + d];
                s[j] += qv.x * kv.x + qv.y * kv.y + qv.z * kv.z + qv.w * kv.w;
            }
        }
#pragma unroll
        for (int j = 0; j < 8; j++) {
            int kglob = k0 + c * 8 + j;
            s[j] = (kglob <= qglob) ? s[j] * 0.125f : -INFINITY;
        }
        float mt = s[0];
#pragma unroll
        for (int j = 1; j < 8; j++) mt = fmaxf(mt, s[j]);
        mt = fmaxf(mt, __shfl_xor_sync(0xffffffffu, mt, 1));
        mt = fmaxf(mt, __shfl_xor_sync(0xffffffffu, mt, 2));
        float mnew = fmaxf(m, mt);
        float corr = expf(m - mnew);
        float ps = 0.f;
#pragma unroll
        for (int j = 0; j < 8; j++) {
            float p = expf(s[j] - mnew);
            Ps[r * 36 + c * 8 + j] = p;
            ps += p;
        }
        ps += __shfl_xor_sync(0xffffffffu, ps, 1);
        ps += __shfl_xor_sync(0xffffffffu, ps, 2);
        l = l * corr + ps;
        m = mnew;
#pragma unroll
        for (int i = 0; i < 16; i++) acc[i] *= corr;
        __syncwarp();
#pragma unroll 4
        for (int kj = 0; kj < 32; kj++) {
            float p = Ps[r * 36 + kj];
#pragma unroll
            for (int i = 0; i < 16; i += 4) {
                float4 vv = *(const float4*)&Vs[kj * 68 + c * 16 + i];
                acc[i]     += p * vv.x;
                acc[i + 1] += p * vv.y;
                acc[i + 2] += p * vv.z;
                acc[i + 3] += p * vv.w;
            }
        }
        __syncwarp();
    }
    float inv = 1.f / l;
    float* orow = out + (size_t)(b * Ss + qt * 64 + r) * Dd + h * HDc + c * 16;
#pragma unroll
    for (int i = 0; i < 16; i++) orow[i] = acc[i] * inv;
}

// ---------------- router ----------------------------------------------------
__global__ __launch_bounds__(256) void router_kernel(const float* __restrict__ g,
                                                     const float* __restrict__ rw)
{
    int t = blockIdx.x;
    float part[Ec] = {};
    for (int d = threadIdx.x; d < Dd; d += 256) {
        float gv = g[(size_t)t * Dd + d];
#pragma unroll
        for (int e = 0; e < Ec; e++) part[e] += gv * rw[d * Ec + e];
    }
#pragma unroll
    for (int e = 0; e < Ec; e++) {
        float v = part[e];
#pragma unroll
        for (int o = 16; o > 0; o >>= 1) v += __shfl_down_sync(0xffffffffu, v, o);
        part[e] = v;
    }
    __shared__ float ws[8][Ec];
    int lane = threadIdx.x & 31, wp = threadIdx.x >> 5;
    if (lane == 0)
        for (int e = 0; e < Ec; e++) ws[wp][e] = part[e];
    __syncthreads();
    if (threadIdx.x == 0) {
        float logit[Ec];
#pragma unroll
        for (int e = 0; e < Ec; e++) {
            float v = 0.f;
            for (int w = 0; w < 8; w++) v += ws[w][e];
            logit[e] = v;
        }
        int i1 = 0;
        for (int e = 1; e < Ec; e++) if (logit[e] > logit[i1]) i1 = e;
        int i2 = (i1 == 0) ? 1 : 0;
        for (int e = 0; e < Ec; e++)
            if (e != i1 && logit[e] > logit[i2]) i2 = e;
        int sel[2] = { i1, i2 };
#pragma unroll
        for (int k = 0; k < 2; k++) {
            int e = sel[k];
            float sgm = 1.f / (1.f + expf(-logit[e]));
            int p = atomicAdd(&g_cnt[e], 1);
            g_rows[e * Tt + p] = t;
            g_wt[e * Tt + p] = sgm;
        }
    }
}

// ---------------- gather ----------------------------------------------------
__global__ __launch_bounds__(256) void gather_kernel(const float* __restrict__ g)
{
    int e = blockIdx.y, p = blockIdx.x;
    if (p >= g_cnt[e]) return;
    int tok = g_rows[e * Tt + p];
    float w = g_wt[e * Tt + p];
    const float* src = g + (size_t)tok * Dd;
    float* dst = g_xe + ((size_t)e * Tt + p) * Dd;
    for (int c = threadIdx.x; c < Dd; c += 256) dst[c] = src[c] * w;
}

// ---------------- expert gate_up grouped GEMM -------------------------------
__global__ __launch_bounds__(256) void expert_gu_gemm(const float* __restrict__ w)
{
    const int e = blockIdx.z;
    if ((int)(blockIdx.y * 128) >= g_cnt[e]) return;
    const int N = 2 * Ii, K = Dd;
    const int n0 = blockIdx.x * 128, m0 = blockIdx.y * 128;
    const float* Ab = g_xe + (size_t)e * Tt * Dd + (size_t)m0 * K;
    const float* Bb_ = w + (size_t)e * Dd * (2 * Ii) + n0;
    float* C = g_gu + (size_t)e * Tt * (2 * Ii);
    MMA_GEMM_BODY(Ab, Bb_, K, N)
#pragma unroll
    for (int mt = 0; mt < 4; mt++) {
#pragma unroll
        for (int nt = 0; nt < 4; nt++) {
            int row0 = m0 + wm * 64 + mt * 16 + g;
            int col  = n0 + wn * 32 + nt * 8 + t * 2;
            *(float2*)(C + (size_t)row0 * N + col) = make_float2(acc[mt][nt][0], acc[mt][nt][1]);
            *(float2*)(C + (size_t)(row0 + 8) * N + col) = make_float2(acc[mt][nt][2], acc[mt][nt][3]);
        }
    }
}

// ---------------- silu(gate)*up for routed experts --------------------------
__global__ __launch_bounds__(256) void expert_hid_kernel()
{
    int e = blockIdx.y, p = blockIdx.x;
    if (p >= g_cnt[e]) return;
    const float* gr = g_gu + ((size_t)e * Tt + p) * (2 * Ii);
    float* hr = g_hid + ((size_t)e * Tt + p) * Ii;
    for (int c = threadIdx.x; c < Ii; c += 256) {
        float gt = gr[c], up = gr[Ii + c];
        hr[c] = gt / (1.f + expf(-gt)) * up;
    }
}

// ---------------- expert down grouped GEMM, scatter-atomic into OUT ---------
__global__ __launch_bounds__(256) void expert_down_gemm(const float* __restrict__ w,
                                                        float* __restrict__ outp)
{
    const int e = blockIdx.z;
    const int cn = g_cnt[e];
    if ((int)(blockIdx.y * 128) >= cn) return;
    const int N = Dd, K = Ii;
    const int n0 = blockIdx.x * 128, m0 = blockIdx.y * 128;
    const float* Ab = g_hid + (size_t)e * Tt * Ii + (size_t)m0 * K;
    const float* Bb_ = w + (size_t)e * Ii * Dd + n0;
    MMA_GEMM_BODY(Ab, Bb_, K, N)
#pragma unroll
    for (int mt = 0; mt < 4; mt++) {
#pragma unroll
        for (int nt = 0; nt < 4; nt++) {
            int row0 = m0 + wm * 64 + mt * 16 + g;
            int col  = n0 + wn * 32 + nt * 8 + t * 2;
            if (row0 < cn) {
                int tok = g_rows[e * Tt + row0];
                atomicAdd(&outp[(size_t)tok * Dd + col],     acc[mt][nt][0]);
                atomicAdd(&outp[(size_t)tok * Dd + col + 1], acc[mt][nt][1]);
            }
            if (row0 + 8 < cn) {
                int tok = g_rows[e * Tt + row0 + 8];
                atomicAdd(&outp[(size_t)tok * Dd + col],     acc[mt][nt][2]);
                atomicAdd(&outp[(size_t)tok * Dd + col + 1], acc[mt][nt][3]);
            }
        }
    }
}

// ---------------- shared-expert silu(gate)*up -------------------------------
__global__ __launch_bounds__(256) void shared_hid_kernel()
{
    size_t n = (size_t)Tt * Ii;
    for (size_t i = blockIdx.x * 256ull + threadIdx.x; i < n; i += (size_t)gridDim.x * 256)
    {
        float gt = g_sg[i], up = g_su[i];
        g_sg[i] = gt / (1.f + expf(-gt)) * up;
    }
}

// ---------------- seed output: out = h1 + shared ----------------------------
__global__ __launch_bounds__(256) void init_out_kernel(float* __restrict__ out)
{
    size_t i4 = blockIdx.x * 256ull + threadIdx.x;
    const float4* a = (const float4*)g_h1;
    const float4* b = (const float4*)g_sh;
    float4 va = a[i4], vb = b[i4];
    ((float4*)out)[i4] = make_float4(va.x + vb.x, va.y + vb.y, va.z + vb.z, va.w + vb.w);
}

// ---------------------------------------------------------------------------
extern "C" void kernel_launch(void* const* d_in, const int* in_sizes, int n_in,
                              void* d_out, int out_size)
{
    const float* x     = (const float*)d_in[0];
    const float* rope  = (const float*)d_in[2];
    const float* w_qkv = (const float*)d_in[4];
    const float* w_o   = (const float*)d_in[5];
    const float* n1w   = (const float*)d_in[6];
    const float* n2w   = (const float*)d_in[7];
    const float* rw    = (const float*)d_in[8];
    const float* w_gu  = (const float*)d_in[9];
    const float* w_dn  = (const float*)d_in[10];
    const float* shg   = (const float*)d_in[11];
    const float* shu   = (const float*)d_in[12];
    const float* shd   = (const float*)d_in[13];
    float* out = (float*)d_out;

    float *bh, *bqkv, *battn, *bh1, *bg, *bsg, *bsu, *bsh;
    int* bcnt;
    cudaGetSymbolAddress((void**)&bh,    g_h);
    cudaGetSymbolAddress((void**)&bqkv,  g_qkv);
    cudaGetSymbolAddress((void**)&battn, g_attn);
    cudaGetSymbolAddress((void**)&bh1,   g_h1);
    cudaGetSymbolAddress((void**)&bg,    g_g);
    cudaGetSymbolAddress((void**)&bsg,   g_sg);
    cudaGetSymbolAddress((void**)&bsu,   g_su);
    cudaGetSymbolAddress((void**)&bsh,   g_sh);
    cudaGetSymbolAddress((void**)&bcnt,  g_cnt);

    // zero expert counters (32 bytes only)
    cudaMemsetAsync(bcnt, 0, Ec * sizeof(int));

    // 1. rmsnorm1
    rmsnorm_kernel<<<Tt, 256>>>(x, n1w, bh);
    // 2. qkv = h @ w_qkv
    mma_gemm_kernel<0><<<dim3(QKVN / 128, Tt / 128), 256>>>(bh, w_qkv, bqkv, nullptr, Tt, QKVN, Dd);
    // 3. rope (q + k in place)
    rope_kernel<<<dim3(Tt, 5), 256>>>(bqkv, rope);
    // 4. attention (static smem, no func attributes)
    attn_kernel<<<dim3(Ss / 64, Hh, Bb), 256>>>(bqkv, battn);
    // 5. h1 = x + attn @ w_o
    mma_gemm_kernel<1><<<dim3(Dd / 128, Tt / 128), 256>>>(battn, w_o, bh1, x, Tt, Dd, Dd);
    // 6. rmsnorm2
    rmsnorm_kernel<<<Tt, 256>>>(bh1, n2w, bg);
    // 7. router (fills g_cnt/g_rows/g_wt)
    router_kernel<<<Tt, 256>>>(bg, rw);
    // 8. gather scaled rows per expert
    gather_kernel<<<dim3(Tt, Ec), 256>>>(bg);
    // 9. shared expert
    mma_gemm_kernel<0><<<dim3(Ii / 128, Tt / 128), 256>>>(bg, shg, bsg, nullptr, Tt, Ii, Dd);
    mma_gemm_kernel<0><<<dim3(Ii / 128, Tt / 128), 256>>>(bg, shu, bsu, nullptr, Tt, Ii, Dd);
    shared_hid_kernel<<<2048, 256>>>();
    mma_gemm_kernel<0><<<dim3(Dd / 128, Tt / 128), 256>>>(bsg, shd, bsh, nullptr, Tt, Dd, Ii);
    // 10. seed out = h1 + shared
    init_out_kernel<<<(Tt * Dd / 4) / 256, 256>>>(out);
    // 11. routed experts
    expert_gu_gemm<<<dim3((2 * Ii) / 128, Tt / 128, Ec), 256>>>(w_gu);
    expert_hid_kernel<<<dim3(Tt, Ec), 256>>>();
    // 12. expert down grouped GEMM -> scatter atomics directly into out
    expert_down_gemm<<<dim3(Dd / 128, Tt / 128, Ec), 256>>>(w_dn, out);
}

// round 13
// speedup vs baseline: 1.6713x; 1.6713x over previous
#include <cuda_runtime.h>
#include <cuda_bf16.h>
#include <math.h>
#include <stdint.h>

// Problem constants
static constexpr int Tt   = 2048;   // B*S tokens
static constexpr int Bb   = 2;
static constexpr int Ss   = 1024;
static constexpr int Dd   = 2048;
static constexpr int Hh   = 32;
static constexpr int HKVc = 8;
static constexpr int HDc  = 64;
static constexpr int QKVN = 3072;   // (H + 2*HKV)*HD
static constexpr int Ii   = 1024;
static constexpr int Ec   = 8;

// ---------------- scratch (device globals; no allocation) ----------------
__device__ float g_h   [(size_t)Tt * Dd];
__device__ float g_qkv [(size_t)Tt * QKVN];
__device__ float g_attn[(size_t)Tt * Dd];
__device__ float g_h1  [(size_t)Tt * Dd];
__device__ float g_g   [(size_t)Tt * Dd];
__device__ float g_sg  [(size_t)Tt * Ii];
__device__ float g_su  [(size_t)Tt * Ii];
__device__ float g_sh  [(size_t)Tt * Dd];
__device__ float g_xe  [(size_t)Ec * Tt * Dd];
__device__ float g_gu  [(size_t)Ec * Tt * 2 * Ii];
__device__ float g_hid [(size_t)Ec * Tt * Ii];
__device__ int   g_cnt [Ec];
__device__ int   g_rows[Ec * Tt];
__device__ float g_wt  [Ec * Tt];

// ---------------- helpers ----------------
__device__ __forceinline__ uint32_t f2tf32(float f) {
    uint32_t r;
    asm("cvt.rna.tf32.f32 %0, %1;" : "=r"(r) : "f"(f));
    return r;
}

// Split fp32 into tf32 hi + tf32 lo (exact residual: hi has low mantissa bits zero)
__device__ __forceinline__ void split_tf32(float v, uint32_t& hi, uint32_t& lo) {
    uint32_t h = f2tf32(v);
    lo = f2tf32(v - __uint_as_float(h));
    hi = h;
}

__device__ __forceinline__ void mma_tf32(float& c0, float& c1, float& c2, float& c3,
                                         uint32_t a0, uint32_t a1, uint32_t a2, uint32_t a3,
                                         uint32_t b0, uint32_t b1) {
    asm volatile("mma.sync.aligned.m16n8k8.row.col.f32.tf32.tf32.f32 "
                 "{%0,%1,%2,%3}, {%4,%5,%6,%7}, {%8,%9}, {%0,%1,%2,%3};"
                 : "+f"(c0), "+f"(c1), "+f"(c2), "+f"(c3)
                 : "r"(a0), "r"(a1), "r"(a2), "r"(a3), "r"(b0), "r"(b1));
}

// ---------------- rmsnorm ----------------
__global__ __launch_bounds__(256) void rmsnorm_kernel(const float* __restrict__ x,
                                                      const float* __restrict__ w,
                                                      float* __restrict__ out)
{
    int t = blockIdx.x;
    const float* xr = x + (size_t)t * Dd;
    float vals[8];
    float ss = 0.f;
#pragma unroll
    for (int i = 0; i < 8; i++) {
        vals[i] = xr[threadIdx.x + i * 256];
        ss += vals[i] * vals[i];
    }
#pragma unroll
    for (int o = 16; o > 0; o >>= 1) ss += __shfl_down_sync(0xffffffffu, ss, o);
    __shared__ float sm[8];
    __shared__ float stot;
    int lane = threadIdx.x & 31, wp = threadIdx.x >> 5;
    if (lane == 0) sm[wp] = ss;
    __syncthreads();
    if (threadIdx.x == 0) {
        float tot = 0.f;
#pragma unroll
        for (int i = 0; i < 8; i++) tot += sm[i];
        stot = rsqrtf(tot / (float)Dd + 1e-5f);
    }
    __syncthreads();
    float sc = stot;
    float* orow = out + (size_t)t * Dd;
#pragma unroll
    for (int i = 0; i < 8; i++) {
        int c = threadIdx.x + i * 256;
        orow[c] = vals[i] * sc * w[c];
    }
}

// =====================================================================
// 3xTF32 tensor-core GEMM (tf32x3 error compensation): fp32-grade accuracy.
// C(128x128) per block, KTILE=16, 256 thr = 8 warps (2m x 4n).
// Warp tile 64x32 = 4x4 m16n8k8 tiles; 3 MMAs per tile-product, issued as
// three term-passes (16 independent-acc MMAs per pass) so the tensor pipe
// sees no RAW chains. Per-accumulator term order (and thus rounding) is
// identical to the round-9-validated kernel:
//   pass1 acc += alo*bhi; pass2 acc += ahi*blo; pass3 acc += ahi*bhi
// A: MxK row-major f32, B: KxN row-major f32. Acc f32.
// Register-prefetch double buffering on global loads.
// Static smem: 2*(128*20 + 16*132)*4 = 37.4 KB (< 48 KB, no attributes).
// =====================================================================
#define MMA_GEMM_BODY(Aptr, Bptr, K_, N_)                                      \
    __shared__ uint32_t Ash[128][20];                                          \
    __shared__ uint32_t Asl[128][20];                                          \
    __shared__ uint32_t Bsh[16][132];                                          \
    __shared__ uint32_t Bsl[16][132];                                          \
    const int tid = threadIdx.x;                                               \
    const int lane = tid & 31, warp = tid >> 5;                                \
    const int wm = warp & 1, wn = warp >> 1;                                   \
    const int g = lane >> 2, t = lane & 3;                                     \
    float acc[4][4][4];                                                        \
    _Pragma("unroll") for (int i_ = 0; i_ < 4; i_++)                           \
    _Pragma("unroll") for (int j_ = 0; j_ < 4; j_++)                           \
    _Pragma("unroll") for (int q_ = 0; q_ < 4; q_++) acc[i_][j_][q_] = 0.f;    \
    float4 pav[2], pbv[2];                                                     \
    _Pragma("unroll")                                                          \
    for (int i = 0; i < 2; i++) {                                              \
        int fi = tid + i * 256;                                                \
        int ra = fi >> 2, ca = (fi & 3) * 4;                                   \
        pav[i] = *(const float4*)((Aptr) + (size_t)ra * (K_) + ca);            \
        int rb = fi >> 5, cb = (fi & 31) * 4;                                  \
        pbv[i] = *(const float4*)((Bptr) + (size_t)rb * (N_) + cb);            \
    }                                                                          \
    for (int k0 = 0; k0 < (K_); k0 += 16) {                                    \
        _Pragma("unroll")                                                      \
        for (int i = 0; i < 2; i++) {                                          \
            int fi = tid + i * 256;                                            \
            int ra = fi >> 2, ca = (fi & 3) * 4;                               \
            split_tf32(pav[i].x, Ash[ra][ca + 0], Asl[ra][ca + 0]);            \
            split_tf32(pav[i].y, Ash[ra][ca + 1], Asl[ra][ca + 1]);            \
            split_tf32(pav[i].z, Ash[ra][ca + 2], Asl[ra][ca + 2]);            \
            split_tf32(pav[i].w, Ash[ra][ca + 3], Asl[ra][ca + 3]);            \
            int rb = fi >> 5, cb = (fi & 31) * 4;                              \
            split_tf32(pbv[i].x, Bsh[rb][cb + 0], Bsl[rb][cb + 0]);            \
            split_tf32(pbv[i].y, Bsh[rb][cb + 1], Bsl[rb][cb + 1]);            \
            split_tf32(pbv[i].z, Bsh[rb][cb + 2], Bsl[rb][cb + 2]);            \
            split_tf32(pbv[i].w, Bsh[rb][cb + 3], Bsl[rb][cb + 3]);            \
        }                                                                      \
        __syncthreads();                                                       \
        if (k0 + 16 < (K_)) {                                                  \
            _Pragma("unroll")                                                  \
            for (int i = 0; i < 2; i++) {                                      \
                int fi = tid + i * 256;                                        \
                int ra = fi >> 2, ca = (fi & 3) * 4;                           \
                pav[i] = *(const float4*)((Aptr) + (size_t)ra * (K_) + k0 + 16 + ca); \
                int rb = fi >> 5, cb = (fi & 31) * 4;                          \
                pbv[i] = *(const float4*)((Bptr) + (size_t)(k0 + 16 + rb) * (N_) + cb); \
            }                                                                  \
        }                                                                      \
        _Pragma("unroll")                                                      \
        for (int kk = 0; kk < 2; kk++) {                                       \
            const int kb = kk * 8;                                             \
            uint32_t ah[4][4], al[4][4];                                       \
            _Pragma("unroll")                                                  \
            for (int mt = 0; mt < 4; mt++) {                                   \
                int rowA = wm * 64 + mt * 16 + g;                              \
                ah[mt][0] = Ash[rowA][kb + t];                                 \
                ah[mt][1] = Ash[rowA + 8][kb + t];                             \
                ah[mt][2] = Ash[rowA][kb + t + 4];                             \
                ah[mt][3] = Ash[rowA + 8][kb + t + 4];                         \
                al[mt][0] = Asl[rowA][kb + t];                                 \
                al[mt][1] = Asl[rowA + 8][kb + t];                             \
                al[mt][2] = Asl[rowA][kb + t + 4];                             \
                al[mt][3] = Asl[rowA + 8][kb + t + 4];                         \
            }                                                                  \
            uint32_t bh[4][2], bl[4][2];                                       \
            _Pragma("unroll")                                                  \
            for (int nt = 0; nt < 4; nt++) {                                   \
                int colB = wn * 32 + nt * 8 + g;                               \
                bh[nt][0] = Bsh[kb + t][colB];                                 \
                bh[nt][1] = Bsh[kb + t + 4][colB];                             \
                bl[nt][0] = Bsl[kb + t][colB];                                 \
                bl[nt][1] = Bsl[kb + t + 4][colB];                             \
            }                                                                  \
            /* pass 1: alo*bhi (16 independent accs) */                        \
            _Pragma("unroll")                                                  \
            for (int mt = 0; mt < 4; mt++)                                     \
                _Pragma("unroll")                                              \
                for (int nt = 0; nt < 4; nt++)                                 \
                    mma_tf32(acc[mt][nt][0], acc[mt][nt][1],                   \
                             acc[mt][nt][2], acc[mt][nt][3],                   \
                             al[mt][0], al[mt][1], al[mt][2], al[mt][3],       \
                             bh[nt][0], bh[nt][1]);                            \
            /* pass 2: ahi*blo */                                              \
            _Pragma("unroll")                                                  \
            for (int mt = 0; mt < 4; mt++)                                     \
                _Pragma("unroll")                                              \
                for (int nt = 0; nt < 4; nt++)                                 \
                    mma_tf32(acc[mt][nt][0], acc[mt][nt][1],                   \
                             acc[mt][nt][2], acc[mt][nt][3],                   \
                             ah[mt][0], ah[mt][1], ah[mt][2], ah[mt][3],       \
                             bl[nt][0], bl[nt][1]);                            \
            /* pass 3: ahi*bhi */                                              \
            _Pragma("unroll")                                                  \
            for (int mt = 0; mt < 4; mt++)                                     \
                _Pragma("unroll")                                              \
                for (int nt = 0; nt < 4; nt++)                                 \
                    mma_tf32(acc[mt][nt][0], acc[mt][nt][1],                   \
                             acc[mt][nt][2], acc[mt][nt][3],                   \
                             ah[mt][0], ah[mt][1], ah[mt][2], ah[mt][3],       \
                             bh[nt][0], bh[nt][1]);                            \
        }                                                                      \
        __syncthreads();                                                       \
    }

// MODE 0: C = A@B ; MODE 1: C = Res + A@B
template <int MODE>
__global__ __launch_bounds__(256) void mma_gemm_kernel(const float* __restrict__ A,
                                                       const float* __restrict__ Bm,
                                                       float* __restrict__ C,
                                                       const float* __restrict__ Res,
                                                       int M, int N, int K)
{
    const int n0 = blockIdx.x * 128, m0 = blockIdx.y * 128;
    const float* Ab = A + (size_t)m0 * K;
    const float* Bb_ = Bm + n0;
    MMA_GEMM_BODY(Ab, Bb_, K, N)
#pragma unroll
    for (int mt = 0; mt < 4; mt++) {
#pragma unroll
        for (int nt = 0; nt < 4; nt++) {
            int row0 = m0 + wm * 64 + mt * 16 + g;
            int col  = n0 + wn * 32 + nt * 8 + t * 2;
            float* p0 = C + (size_t)row0 * N + col;
            float* p1 = C + (size_t)(row0 + 8) * N + col;
            if (MODE == 0) {
                *(float2*)p0 = make_float2(acc[mt][nt][0], acc[mt][nt][1]);
                *(float2*)p1 = make_float2(acc[mt][nt][2], acc[mt][nt][3]);
            } else {
                const float* r0 = Res + (size_t)row0 * N + col;
                const float* r1 = Res + (size_t)(row0 + 8) * N + col;
                float2 v0 = *(const float2*)r0, v1 = *(const float2*)r1;
                *(float2*)p0 = make_float2(acc[mt][nt][0] + v0.x, acc[mt][nt][1] + v0.y);
                *(float2*)p1 = make_float2(acc[mt][nt][2] + v1.x, acc[mt][nt][3] + v1.y);
            }
        }
    }
}

// ---------------- RoPE on q (heads 0..31) and k (heads 32..39) --------------
__global__ __launch_bounds__(256) void rope_kernel(float* __restrict__ qkv,
                                                   const float* __restrict__ cache)
{
    int t = blockIdx.x;
    int s = t & (Ss - 1);
    int pi = blockIdx.y * 256 + threadIdx.x;
    if (pi >= (Hh + HKVc) * (HDc / 2)) return;
    int head = pi >> 5;
    int i = pi & 31;
    int col = (head < Hh) ? head * HDc + 2 * i
                          : Hh * HDc + (head - Hh) * HDc + 2 * i;
    float* p = qkv + (size_t)t * QKVN + col;
    float c  = cache[s * HDc + 2 * i];
    float sn = cache[s * HDc + 2 * i + 1];
    float x0 = p[0], x1 = p[1];
    p[0] = x0 * c - x1 * sn;
    p[1] = x1 * c + x0 * sn;
}

// ---------------- flash attention, static smem (<=48KB), KT=32 --------------
__global__ __launch_bounds__(256) void attn_kernel(const float* __restrict__ qkv,
                                                   float* __restrict__ out)
{
    __shared__ float Qs[64 * 68];
    __shared__ float Ks[32 * 68];
    __shared__ float Vs[32 * 68];
    __shared__ float Ps[64 * 36];
    const int qt = blockIdx.x, h = blockIdx.y, b = blockIdx.z;
    const int kvh = h >> 2;
    const int tid = threadIdx.x;
    const int r = tid >> 2, c = tid & 3;
    const int qcol = h * HDc;
    const int kcol = Hh * HDc + kvh * HDc;
    const int vcol = (Hh + HKVc) * HDc + kvh * HDc;

#pragma unroll
    for (int v = 0; v < 4; v++) {
        int fi = tid + v * 256;
        int rr = fi >> 4, c4 = (fi & 15) * 4;
        *(float4*)&Qs[rr * 68 + c4] =
            *(const float4*)(qkv + (size_t)(b * Ss + qt * 64 + rr) * QKVN + qcol + c4);
    }

    float m = -INFINITY, l = 0.f;
    float acc[16];
#pragma unroll
    for (int i = 0; i < 16; i++) acc[i] = 0.f;

    const int ntiles = 2 * (qt + 1);
    const int qglob = qt * 64 + r;
    for (int kt = 0; kt < ntiles; kt++) {
        const int k0 = kt * 32;
        __syncthreads();
#pragma unroll
        for (int v = 0; v < 2; v++) {
            int fi = tid + v * 256;
            int rr = fi >> 4, c4 = (fi & 15) * 4;
            size_t base = (size_t)(b * Ss + k0 + rr) * QKVN;
            *(float4*)&Ks[rr * 68 + c4] = *(const float4*)(qkv + base + kcol + c4);
            *(float4*)&Vs[rr * 68 + c4] = *(const float4*)(qkv + base + vcol + c4);
        }
        __syncthreads();

        float s[8];
#pragma unroll
        for (int j = 0; j < 8; j++) s[j] = 0.f;
#pragma unroll 4
        for (int d = 0; d < 64; d += 4) {
            float4 qv = *(const float4*)&Qs[r * 68 + d];
#pragma unroll
            for (int j = 0; j < 8; j++) {
                float4 kv = *(const float4*)&Ks[(c * 8 + j) * 68 + d];
                s[j] += qv.x * kv.x + qv.y * kv.y + qv.z * kv.z + qv.w * kv.w;
            }
        }
#pragma unroll
        for (int j = 0; j < 8; j++) {
            int kglob = k0 + c * 8 + j;
            s[j] = (kglob <= qglob) ? s[j] * 0.125f : -INFINITY;
        }
        float mt = s[0];
#pragma unroll
        for (int j = 1; j < 8; j++) mt = fmaxf(mt, s[j]);
        mt = fmaxf(mt, __shfl_xor_sync(0xffffffffu, mt, 1));
        mt = fmaxf(mt, __shfl_xor_sync(0xffffffffu, mt, 2));
        float mnew = fmaxf(m, mt);
        float corr = expf(m - mnew);
        float ps = 0.f;
#pragma unroll
        for (int j = 0; j < 8; j++) {
            float p = expf(s[j] - mnew);
            Ps[r * 36 + c * 8 + j] = p;
            ps += p;
        }
        ps += __shfl_xor_sync(0xffffffffu, ps, 1);
        ps += __shfl_xor_sync(0xffffffffu, ps, 2);
        l = l * corr + ps;
        m = mnew;
#pragma unroll
        for (int i = 0; i < 16; i++) acc[i] *= corr;
        __syncwarp();
#pragma unroll 4
        for (int kj = 0; kj < 32; kj++) {
            float p = Ps[r * 36 + kj];
#pragma unroll
            for (int i = 0; i < 16; i += 4) {
                float4 vv = *(const float4*)&Vs[kj * 68 + c * 16 + i];
                acc[i]     += p * vv.x;
                acc[i + 1] += p * vv.y;
                acc[i + 2] += p * vv.z;
                acc[i + 3] += p * vv.w;
            }
        }
        __syncwarp();
    }
    float inv = 1.f / l;
    float* orow = out + (size_t)(b * Ss + qt * 64 + r) * Dd + h * HDc + c * 16;
#pragma unroll
    for (int i = 0; i < 16; i++) orow[i] = acc[i] * inv;
}

// ---------------- router ----------------------------------------------------
__global__ __launch_bounds__(256) void router_kernel(const float* __restrict__ g,
                                                     const float* __restrict__ rw)
{
    int t = blockIdx.x;
    float part[Ec] = {};
    for (int d = threadIdx.x; d < Dd; d += 256) {
        float gv = g[(size_t)t * Dd + d];
#pragma unroll
        for (int e = 0; e < Ec; e++) part[e] += gv * rw[d * Ec + e];
    }
#pragma unroll
    for (int e = 0; e < Ec; e++) {
        float v = part[e];
#pragma unroll
        for (int o = 16; o > 0; o >>= 1) v += __shfl_down_sync(0xffffffffu, v, o);
        part[e] = v;
    }
    __shared__ float ws[8][Ec];
    int lane = threadIdx.x & 31, wp = threadIdx.x >> 5;
    if (lane == 0)
        for (int e = 0; e < Ec; e++) ws[wp][e] = part[e];
    __syncthreads();
    if (threadIdx.x == 0) {
        float logit[Ec];
#pragma unroll
        for (int e = 0; e < Ec; e++) {
            float v = 0.f;
            for (int w = 0; w < 8; w++) v += ws[w][e];
            logit[e] = v;
        }
        int i1 = 0;
        for (int e = 1; e < Ec; e++) if (logit[e] > logit[i1]) i1 = e;
        int i2 = (i1 == 0) ? 1 : 0;
        for (int e = 0; e < Ec; e++)
            if (e != i1 && logit[e] > logit[i2]) i2 = e;
        int sel[2] = { i1, i2 };
#pragma unroll
        for (int k = 0; k < 2; k++) {
            int e = sel[k];
            float sgm = 1.f / (1.f + expf(-logit[e]));
            int p = atomicAdd(&g_cnt[e], 1);
            g_rows[e * Tt + p] = t;
            g_wt[e * Tt + p] = sgm;
        }
    }
}

// ---------------- gather ----------------------------------------------------
__global__ __launch_bounds__(256) void gather_kernel(const float* __restrict__ g)
{
    int e = blockIdx.y, p = blockIdx.x;
    if (p >= g_cnt[e]) return;
    int tok = g_rows[e * Tt + p];
    float w = g_wt[e * Tt + p];
    const float* src = g + (size_t)tok * Dd;
    float* dst = g_xe + ((size_t)e * Tt + p) * Dd;
    for (int c = threadIdx.x; c < Dd; c += 256) dst[c] = src[c] * w;
}

// ---------------- expert gate_up grouped GEMM -------------------------------
__global__ __launch_bounds__(256) void expert_gu_gemm(const float* __restrict__ w)
{
    const int e = blockIdx.z;
    if ((int)(blockIdx.y * 128) >= g_cnt[e]) return;
    const int N = 2 * Ii, K = Dd;
    const int n0 = blockIdx.x * 128, m0 = blockIdx.y * 128;
    const float* Ab = g_xe + (size_t)e * Tt * Dd + (size_t)m0 * K;
    const float* Bb_ = w + (size_t)e * Dd * (2 * Ii) + n0;
    float* C = g_gu + (size_t)e * Tt * (2 * Ii);
    MMA_GEMM_BODY(Ab, Bb_, K, N)
#pragma unroll
    for (int mt = 0; mt < 4; mt++) {
#pragma unroll
        for (int nt = 0; nt < 4; nt++) {
            int row0 = m0 + wm * 64 + mt * 16 + g;
            int col  = n0 + wn * 32 + nt * 8 + t * 2;
            *(float2*)(C + (size_t)row0 * N + col) = make_float2(acc[mt][nt][0], acc[mt][nt][1]);
            *(float2*)(C + (size_t)(row0 + 8) * N + col) = make_float2(acc[mt][nt][2], acc[mt][nt][3]);
        }
    }
}

// ---------------- silu(gate)*up for routed experts --------------------------
__global__ __launch_bounds__(256) void expert_hid_kernel()
{
    int e = blockIdx.y, p = blockIdx.x;
    if (p >= g_cnt[e]) return;
    const float* gr = g_gu + ((size_t)e * Tt + p) * (2 * Ii);
    float* hr = g_hid + ((size_t)e * Tt + p) * Ii;
    for (int c = threadIdx.x; c < Ii; c += 256) {
        float gt = gr[c], up = gr[Ii + c];
        hr[c] = gt / (1.f + expf(-gt)) * up;
    }
}

// ---------------- expert down grouped GEMM, scatter-atomic into OUT ---------
__global__ __launch_bounds__(256) void expert_down_gemm(const float* __restrict__ w,
                                                        float* __restrict__ outp)
{
    const int e = blockIdx.z;
    const int cn = g_cnt[e];
    if ((int)(blockIdx.y * 128) >= cn) return;
    const int N = Dd, K = Ii;
    const int n0 = blockIdx.x * 128, m0 = blockIdx.y * 128;
    const float* Ab = g_hid + (size_t)e * Tt * Ii + (size_t)m0 * K;
    const float* Bb_ = w + (size_t)e * Ii * Dd + n0;
    MMA_GEMM_BODY(Ab, Bb_, K, N)
#pragma unroll
    for (int mt = 0; mt < 4; mt++) {
#pragma unroll
        for (int nt = 0; nt < 4; nt++) {
            int row0 = m0 + wm * 64 + mt * 16 + g;
            int col  = n0 + wn * 32 + nt * 8 + t * 2;
            if (row0 < cn) {
                int tok = g_rows[e * Tt + row0];
                atomicAdd(&outp[(size_t)tok * Dd + col],     acc[mt][nt][0]);
                atomicAdd(&outp[(size_t)tok * Dd + col + 1], acc[mt][nt][1]);
            }
            if (row0 + 8 < cn) {
                int tok = g_rows[e * Tt + row0 + 8];
                atomicAdd(&outp[(size_t)tok * Dd + col],     acc[mt][nt][2]);
                atomicAdd(&outp[(size_t)tok * Dd + col + 1], acc[mt][nt][3]);
            }
        }
    }
}

// ---------------- shared-expert silu(gate)*up -------------------------------
__global__ __launch_bounds__(256) void shared_hid_kernel()
{
    size_t n = (size_t)Tt * Ii;
    for (size_t i = blockIdx.x * 256ull + threadIdx.x; i < n; i += (size_t)gridDim.x * 256)
    {
        float gt = g_sg[i], up = g_su[i];
        g_sg[i] = gt / (1.f + expf(-gt)) * up;
    }
}

// ---------------- seed output: out = h1 + shared ----------------------------
__global__ __launch_bounds__(256) void init_out_kernel(float* __restrict__ out)
{
    size_t i4 = blockIdx.x * 256ull + threadIdx.x;
    const float4* a = (const float4*)g_h1;
    const float4* b = (const float4*)g_sh;
    float4 va = a[i4], vb = b[i4];
    ((float4*)out)[i4] = make_float4(va.x + vb.x, va.y + vb.y, va.z + vb.z, va.w + vb.w);
}

// ---------------------------------------------------------------------------
extern "C" void kernel_launch(void* const* d_in, const int* in_sizes, int n_in,
                              void* d_out, int out_size)
{
    const float* x     = (const float*)d_in[0];
    const float* rope  = (const float*)d_in[2];
    const float* w_qkv = (const float*)d_in[4];
    const float* w_o   = (const float*)d_in[5];
    const float* n1w   = (const float*)d_in[6];
    const float* n2w   = (const float*)d_in[7];
    const float* rw    = (const float*)d_in[8];
    const float* w_gu  = (const float*)d_in[9];
    const float* w_dn  = (const float*)d_in[10];
    const float* shg   = (const float*)d_in[11];
    const float* shu   = (const float*)d_in[12];
    const float* shd   = (const float*)d_in[13];
    float* out = (float*)d_out;

    float *bh, *bqkv, *battn, *bh1, *bg, *bsg, *bsu, *bsh;
    int* bcnt;
    cudaGetSymbolAddress((void**)&bh,    g_h);
    cudaGetSymbolAddress((void**)&bqkv,  g_qkv);
    cudaGetSymbolAddress((void**)&battn, g_attn);
    cudaGetSymbolAddress((void**)&bh1,   g_h1);
    cudaGetSymbolAddress((void**)&bg,    g_g);
    cudaGetSymbolAddress((void**)&bsg,   g_sg);
    cudaGetSymbolAddress((void**)&bsu,   g_su);
    cudaGetSymbolAddress((void**)&bsh,   g_sh);
    cudaGetSymbolAddress((void**)&bcnt,  g_cnt);

    // 1. rmsnorm1
    rmsnorm_kernel<<<Tt, 256>>>(x, n1w, bh);
    // 2. qkv = h @ w_qkv
    mma_gemm_kernel<0><<<dim3(QKVN / 128, Tt / 128), 256>>>(bh, w_qkv, bqkv, nullptr, Tt, QKVN, Dd);
    // 3. rope (q + k in place)
    rope_kernel<<<dim3(Tt, 5), 256>>>(bqkv, rope);
    // 4. attention (static smem, no func attributes)
    attn_kernel<<<dim3(Ss / 64, Hh, Bb), 256>>>(bqkv, battn);
    // 5. h1 = x + attn @ w_o   <-- target of the ncu capture slot this round
    mma_gemm_kernel<1><<<dim3(Dd / 128, Tt / 128), 256>>>(battn, w_o, bh1, x, Tt, Dd, Dd);
    // 6. rmsnorm2
    rmsnorm_kernel<<<Tt, 256>>>(bh1, n2w, bg);
    // 7. zero expert counters (placed here: only router needs it; shifts launch
    //    indices so the ncu -s window lands on a GEMM instead of attention)
    cudaMemsetAsync(bcnt, 0, Ec * sizeof(int));
    // 8. router (fills g_cnt/g_rows/g_wt)
    router_kernel<<<Tt, 256>>>(bg, rw);
    // 9. gather scaled rows per expert
    gather_kernel<<<dim3(Tt, Ec), 256>>>(bg);
    // 10. shared expert
    mma_gemm_kernel<0><<<dim3(Ii / 128, Tt / 128), 256>>>(bg, shg, bsg, nullptr, Tt, Ii, Dd);
    mma_gemm_kernel<0><<<dim3(Ii / 128, Tt / 128), 256>>>(bg, shu, bsu, nullptr, Tt, Ii, Dd);
    shared_hid_kernel<<<2048, 256>>>();
    mma_gemm_kernel<0><<<dim3(Dd / 128, Tt / 128), 256>>>(bsg, shd, bsh, nullptr, Tt, Dd, Ii);
    // 11. seed out = h1 + shared
    init_out_kernel<<<(Tt * Dd / 4) / 256, 256>>>(out);
    // 12. routed experts
    expert_gu_gemm<<<dim3((2 * Ii) / 128, Tt / 128, Ec), 256>>>(w_gu);
    expert_hid_kernel<<<dim3(Tt, Ec), 256>>>();
    // 13. expert down grouped GEMM -> scatter atomics directly into out
    expert_down_gemm<<<dim3(Dd / 128, Tt / 128, Ec), 256>>>(w_dn, out);
}